// round 1
// baseline (speedup 1.0000x reference)
#include <cuda_runtime.h>
#include <math.h>

#define BB    32
#define NN    1000
#define FF    128
#define NODES 32000
#define MAXD  128

// ---------------- scratch (static __device__, no allocation) ----------------
__device__ unsigned short g_nbr[(size_t)NODES * MAXD]; // adjacency lists (col idx within batch)
__device__ int            g_deg[NODES];
__device__ float          g_m[NODES];     // current mask (0/1)
__device__ float          g_c[NODES];     // per-node input scale (mask * tanh(y) chain)
__device__ float          g_D[NODES];     // D_i = (deg_hat + 1e-5)^-0.5
__device__ float          g_w[NODES];     // gather weight = D_i * c_i
__device__ float          g_y[NODES];     // pooling scores
__device__ float          g_hA[(size_t)NODES * FF];
__device__ float          g_hB[(size_t)NODES * FF];
__device__ float          g_Wt[3 * FF * FF]; // transposed weights Wt[l][k*128 + t] = W_l[t][k]

// ---------------- init: masks, scales, weight transpose ----------------
__global__ void k_init(const float* __restrict__ mask,
                       const float* __restrict__ W0,
                       const float* __restrict__ W1,
                       const float* __restrict__ W2) {
    int idx = blockIdx.x * 256 + threadIdx.x;
    if (idx < NODES) { g_m[idx] = mask[idx]; g_c[idx] = 1.0f; }
    if (idx < 3 * FF * FF) {
        int l = idx / (FF * FF);
        int r = idx - l * FF * FF;
        int k = r / FF;
        int t = r - k * FF;
        const float* W = (l == 0) ? W0 : ((l == 1) ? W1 : W2);
        g_Wt[idx] = W[t * FF + k];
    }
}

// ---------------- build adjacency lists: one warp per A row ----------------
__global__ void k_build(const float* __restrict__ A) {
    int row  = blockIdx.x * 8 + (threadIdx.x >> 5);
    int lane = threadIdx.x & 31;
    const float* ar = A + (size_t)row * NN;
    unsigned short* nb = g_nbr + (size_t)row * MAXD;
    int deg = 0;
    for (int base = 0; base < NN; base += 32) {
        int c = base + lane;
        float v = (c < NN) ? ar[c] : 0.0f;
        unsigned bal = __ballot_sync(0xffffffffu, v != 0.0f);
        if (v != 0.0f) {
            int off = __popc(bal & ((1u << lane) - 1u));
            if (deg + off < MAXD) nb[deg + off] = (unsigned short)c;
        }
        deg += __popc(bal);
    }
    if (lane == 0) g_deg[row] = (deg < MAXD) ? deg : MAXD;
}

// ---------------- per-layer: degrees -> D, gather weight w = D*c ----------------
__global__ void k_degD() {
    int node = blockIdx.x * 256 + threadIdx.x;
    if (node >= NODES) return;
    int b1000 = (node / NN) * NN;
    int deg = g_deg[node];
    const unsigned short* nb = g_nbr + (size_t)node * MAXD;
    float s = 1.0f; // self loop from A+I
    #pragma unroll 4
    for (int k = 0; k < deg; k++) s += g_m[b1000 + nb[k]];
    float D = 1.0f / sqrtf(s + 1e-5f);
    g_D[node] = D;
    g_w[node] = D * g_c[node];
}

// ---------------- fused sparse L@x + Linear + ReLU + mask ----------------
// block = 256 threads, 32 nodes per block. Phase1: warp-per-node gather into
// smem s[32][132]. Phase2: register-tiled (4x4) GEMM vs smem-resident Wt.
__global__ void k_gconv(const float* __restrict__ x_in, int in_sel, int out_sel,
                        int layer, const float* __restrict__ bias) {
    extern __shared__ float sm[];
    float* Ws = sm;                 // 128*128 floats (transposed W)
    float* sS = sm + FF * FF;       // 32 * 132 floats (padded rows)

    const float* in  = (in_sel == 0) ? x_in : ((in_sel == 1) ? g_hA : g_hB);
    float*       out = (out_sel == 1) ? g_hA : g_hB;

    int tid = threadIdx.x;
    const float* Wsrc = g_Wt + layer * FF * FF;
    for (int i = tid; i < FF * FF; i += 256) Ws[i] = Wsrc[i];

    int wid = tid >> 5, lane = tid & 31;
    int blockStart = blockIdx.x * 32;

    // ---- Phase 1: gather ----
    for (int q = 0; q < 4; q++) {
        int lr = wid * 4 + q;
        int node = blockStart + lr;
        float4 a0 = make_float4(0.f, 0.f, 0.f, 0.f);
        float4 a1 = make_float4(0.f, 0.f, 0.f, 0.f);
        float m = g_m[node];
        if (m != 0.0f) {
            int b1000 = (node / NN) * NN;
            float D  = g_D[node];
            float wi = g_w[node];
            float4 xv = ((const float4*)(in + (size_t)node * FF))[lane];
            a0.x = wi * xv.x; a0.y = wi * xv.y; a0.z = wi * xv.z; a0.w = wi * xv.w;
            int deg = g_deg[node];
            const unsigned short* nb = g_nbr + (size_t)node * MAXD;
            for (int base = 0; base < deg; base += 32) {
                int lim = deg - base; if (lim > 32) lim = 32;
                int myj = 0;
                if (lane < lim) myj = nb[base + lane];
                int t = 0;
                for (; t + 1 < lim; t += 2) {
                    int j0 = __shfl_sync(0xffffffffu, myj, t);
                    int j1 = __shfl_sync(0xffffffffu, myj, t + 1);
                    float w0 = g_w[b1000 + j0];
                    float w1 = g_w[b1000 + j1];
                    float4 v0 = ((const float4*)(in + (size_t)(b1000 + j0) * FF))[lane];
                    float4 v1 = ((const float4*)(in + (size_t)(b1000 + j1) * FF))[lane];
                    a0.x += w0 * v0.x; a0.y += w0 * v0.y; a0.z += w0 * v0.z; a0.w += w0 * v0.w;
                    a1.x += w1 * v1.x; a1.y += w1 * v1.y; a1.z += w1 * v1.z; a1.w += w1 * v1.w;
                }
                if (t < lim) {
                    int j0 = __shfl_sync(0xffffffffu, myj, t);
                    float w0 = g_w[b1000 + j0];
                    float4 v0 = ((const float4*)(in + (size_t)(b1000 + j0) * FF))[lane];
                    a0.x += w0 * v0.x; a0.y += w0 * v0.y; a0.z += w0 * v0.z; a0.w += w0 * v0.w;
                }
            }
            a0.x = D * (a0.x + a1.x);
            a0.y = D * (a0.y + a1.y);
            a0.z = D * (a0.z + a1.z);
            a0.w = D * (a0.w + a1.w);
        }
        ((float4*)(sS + lr * 132))[lane] = a0;
    }
    __syncthreads();

    // ---- Phase 2: GEMM 32x128 = s(32x128) @ W^T, register tile 4x4 ----
    int tx = tid & 31, ty = tid >> 5;
    float acc[4][4];
    #pragma unroll
    for (int j = 0; j < 4; j++)
        #pragma unroll
        for (int c = 0; c < 4; c++) acc[j][c] = 0.0f;

    const float4* W4 = (const float4*)Ws;
    #pragma unroll 4
    for (int k = 0; k < FF; k++) {
        float4 wv = W4[k * 32 + tx];
        float b0 = sS[(ty * 4 + 0) * 132 + k];
        float b1 = sS[(ty * 4 + 1) * 132 + k];
        float b2 = sS[(ty * 4 + 2) * 132 + k];
        float b3 = sS[(ty * 4 + 3) * 132 + k];
        acc[0][0] += b0 * wv.x; acc[0][1] += b0 * wv.y; acc[0][2] += b0 * wv.z; acc[0][3] += b0 * wv.w;
        acc[1][0] += b1 * wv.x; acc[1][1] += b1 * wv.y; acc[1][2] += b1 * wv.z; acc[1][3] += b1 * wv.w;
        acc[2][0] += b2 * wv.x; acc[2][1] += b2 * wv.y; acc[2][2] += b2 * wv.z; acc[2][3] += b2 * wv.w;
        acc[3][0] += b3 * wv.x; acc[3][1] += b3 * wv.y; acc[3][2] += b3 * wv.z; acc[3][3] += b3 * wv.w;
    }

    float4 bias4 = ((const float4*)bias)[tx];
    #pragma unroll
    for (int j = 0; j < 4; j++) {
        int node = blockStart + ty * 4 + j;
        float m = g_m[node];
        float4 o;
        o.x = fmaxf(acc[j][0] + bias4.x, 0.0f) * m;
        o.y = fmaxf(acc[j][1] + bias4.y, 0.0f) * m;
        o.z = fmaxf(acc[j][2] + bias4.z, 0.0f) * m;
        o.w = fmaxf(acc[j][3] + bias4.w, 0.0f) * m;
        ((float4*)(out + (size_t)node * FF))[tx] = o;
    }
}

// ---------------- pooling scores: y = (h @ p) / ||p|| ----------------
__global__ void k_score(int in_sel, const float* __restrict__ p) {
    int gw = blockIdx.x * 8 + (threadIdx.x >> 5);
    if (gw >= NODES) return;
    const float* h = (in_sel == 1) ? g_hA : g_hB;
    int lane = threadIdx.x & 31;
    float s1 = 0.f, s2 = 0.f;
    #pragma unroll
    for (int q = 0; q < 4; q++) {
        int k = lane + 32 * q;
        float pv = p[k];
        float hv = h[(size_t)gw * FF + k];
        s1 += hv * pv;
        s2 += pv * pv;
    }
    #pragma unroll
    for (int o = 16; o; o >>= 1) {
        s1 += __shfl_xor_sync(0xffffffffu, s1, o);
        s2 += __shfl_xor_sync(0xffffffffu, s2, o);
    }
    if (lane == 0) g_y[gw] = s1 / sqrtf(s2);
}

// ---------------- pooling: stable rank, drop N_remove lowest; update m, c ----------------
__global__ void k_pool(const int* __restrict__ N_nodes, int first) {
    __shared__ float key[NN];
    int b = blockIdx.x, i = threadIdx.x;
    int node = b * NN + i;
    float m = 0.f, yv = 0.f;
    if (i < NN) {
        m  = g_m[node];
        yv = g_y[node];
        key[i] = (m > 0.f) ? yv : __int_as_float(0x7f800000); // +inf for invalid
    }
    __syncthreads();
    if (i >= NN) return;

    int Nn  = N_nodes[b];
    int Nr1 = (int)((float)Nn * 0.2f);                    // matches astype(int32) truncation
    int Nr  = first ? Nr1 : (int)((float)(Nn - Nr1) * 0.2f);

    if (m > 0.f) {
        float ki = key[i];
        int cnt = 0;
        #pragma unroll 4
        for (int j = 0; j < NN; j++) {
            float kj = key[j];
            cnt += (kj < ki) || (kj == ki && j < i);      // stable ascending rank
        }
        bool keep = (cnt >= Nr);
        g_m[node] = keep ? 1.0f : 0.0f;
        g_c[node] = keep ? tanhf(yv) : 0.0f;
    } else {
        g_m[node] = 0.0f;
        g_c[node] = 0.0f;
    }
}

// ---------------- global max pool + FC ----------------
__global__ void k_final(const float* __restrict__ Wfc, const float* __restrict__ bfc,
                        float* __restrict__ outp) {
    __shared__ float g[FF];
    int b = blockIdx.x, f = threadIdx.x; // 128 threads
    const float* hb = g_hA + (size_t)b * NN * FF + f;
    float mx = 0.0f; // relu*mask => all entries >= 0, masked rows are exactly 0
    #pragma unroll 4
    for (int i = 0; i < NN; i++) mx = fmaxf(mx, hb[(size_t)i * FF]);
    g[f] = mx;
    __syncthreads();
    if (f < 64) {
        float s = bfc[f];
        #pragma unroll 4
        for (int k = 0; k < FF; k++) s += g[k] * Wfc[f * FF + k];
        outp[b * 64 + f] = s;
    }
}

// ---------------- launch ----------------
extern "C" void kernel_launch(void* const* d_in, const int* in_sizes, int n_in,
                              void* d_out, int out_size) {
    const float* x    = (const float*)d_in[0];
    const float* A    = (const float*)d_in[1];
    const float* mask = (const float*)d_in[2];
    const int*   Nn   = (const int*)d_in[3];
    const float* W0   = (const float*)d_in[4];
    const float* b0   = (const float*)d_in[5];
    const float* W1   = (const float*)d_in[6];
    const float* b1   = (const float*)d_in[7];
    const float* W2   = (const float*)d_in[8];
    const float* b2   = (const float*)d_in[9];
    const float* p0   = (const float*)d_in[10];
    const float* p1   = (const float*)d_in[11];
    const float* Wfc  = (const float*)d_in[12];
    const float* bfc  = (const float*)d_in[13];
    float* outp = (float*)d_out;

    size_t smem = (size_t)(FF * FF + 32 * 132) * sizeof(float); // 82,432 B
    cudaFuncSetAttribute(k_gconv, cudaFuncAttributeMaxDynamicSharedMemorySize, (int)smem);

    k_init <<<192, 256>>>(mask, W0, W1, W2);
    k_build<<<4000, 256>>>(A);

    // layer 0
    k_degD <<<125, 256>>>();
    k_gconv<<<1000, 256, smem>>>(x, 0, 1, 0, b0);   // x -> hA
    k_score<<<4000, 256>>>(1, p0);
    k_pool <<<32, 1024>>>(Nn, 1);

    // layer 1
    k_degD <<<125, 256>>>();
    k_gconv<<<1000, 256, smem>>>(x, 1, 2, 1, b1);   // hA -> hB
    k_score<<<4000, 256>>>(2, p1);
    k_pool <<<32, 1024>>>(Nn, 0);

    // layer 2
    k_degD <<<125, 256>>>();
    k_gconv<<<1000, 256, smem>>>(x, 2, 1, 2, b2);   // hB -> hA

    k_final<<<32, 128>>>(Wfc, bfc, outp);
}

// round 2
// speedup vs baseline: 1.5036x; 1.5036x over previous
#include <cuda_runtime.h>
#include <math.h>

#define BB    32
#define NN    1000
#define FF    128
#define NODES 32000
#define MAXD  128

// ---------------- scratch (static __device__, no allocation) ----------------
__device__ unsigned short g_nbr[(size_t)NODES * MAXD];
__device__ int            g_deg[NODES];
__device__ float          g_m[NODES];     // current mask (0/1)
__device__ float          g_c[NODES];     // per-node input scale (tanh(y) chain)
__device__ float          g_D[NODES];     // D_i = (deg_hat + 1e-5)^-0.5
__device__ float          g_w[NODES];     // gather weight = D_i * c_i
__device__ float          g_y[NODES];     // pooling scores
__device__ float          g_hA[(size_t)NODES * FF];
__device__ float          g_hB[(size_t)NODES * FF];
__device__ float          g_Wt[3 * FF * FF]; // Wt[l][k*128 + t] = W_l[t][k]

// ---------------- init: masks, scales, weight transpose ----------------
__global__ void k_init(const float* __restrict__ mask,
                       const float* __restrict__ W0,
                       const float* __restrict__ W1,
                       const float* __restrict__ W2) {
    int idx = blockIdx.x * 256 + threadIdx.x;
    if (idx < NODES) { g_m[idx] = mask[idx]; g_c[idx] = 1.0f; }
    if (idx < 3 * FF * FF) {
        int l = idx / (FF * FF);
        int r = idx - l * FF * FF;
        int k = r / FF;
        int t = r - k * FF;
        const float* W = (l == 0) ? W0 : ((l == 1) ? W1 : W2);
        g_Wt[idx] = W[t * FF + k];
    }
}

// ---------------- build adjacency lists: warp per row, float4 + warp scan ----
__global__ void k_build(const float* __restrict__ A) {
    int row  = blockIdx.x * 8 + (threadIdx.x >> 5);
    int lane = threadIdx.x & 31;
    const float4* ar = (const float4*)(A + (size_t)row * NN);
    unsigned short* nb = g_nbr + (size_t)row * MAXD;
    int deg = 0;
    for (int base = 0; base < NN; base += 128) {       // 32 lanes x 4 cols
        int col = base + 4 * lane;
        float4 v = make_float4(0.f, 0.f, 0.f, 0.f);
        if (col < NN) v = __ldg(ar + (col >> 2));
        unsigned bits = (v.x != 0.f ? 1u : 0u) | (v.y != 0.f ? 2u : 0u)
                      | (v.z != 0.f ? 4u : 0u) | (v.w != 0.f ? 8u : 0u);
        int c = __popc(bits);
        int pre = c;
        #pragma unroll
        for (int off = 1; off < 32; off <<= 1) {
            int t = __shfl_up_sync(0xffffffffu, pre, off);
            if (lane >= off) pre += t;
        }
        int tot = __shfl_sync(0xffffffffu, pre, 31);
        int pos = deg + (pre - c);
        #pragma unroll
        for (int k = 0; k < 4; k++) {
            if (bits & (1u << k)) {
                if (pos < MAXD) nb[pos] = (unsigned short)(col + k);
                pos++;
            }
        }
        deg += tot;
    }
    if (lane == 0) g_deg[row] = (deg < MAXD) ? deg : MAXD;
}

// ---------------- per-layer: degrees -> D, gather weight w = D*c -------------
__global__ void k_degD() {
    int node = blockIdx.x * 256 + threadIdx.x;
    if (node >= NODES) return;
    int b1000 = (node / NN) * NN;
    int deg = g_deg[node];
    const unsigned short* nb = g_nbr + (size_t)node * MAXD;
    float s = 1.0f; // self loop
    #pragma unroll 4
    for (int k = 0; k < deg; k++) s += g_m[b1000 + nb[k]];
    float D = 1.0f / sqrtf(s + 1e-5f);
    g_D[node] = D;
    g_w[node] = D * g_c[node];
}

// ---------------- fused sparse L@x + Linear + ReLU + mask (+ scores) ---------
// block = 256 threads, 32 nodes. Phase1: warp-per-node gather into smem.
// Phase2: 4x4 register-tile GEMM; W served from L1 (__ldg), not smem.
// Epilogue: optional pooling score y = (h@p)/||p|| via warp reduction.
__global__ void __launch_bounds__(256) k_gconv(
        const float* __restrict__ x_in, int in_sel, int out_sel,
        int layer, const float* __restrict__ bias, const float* __restrict__ p) {
    __shared__ float sS[32 * 132];

    const float* in  = (in_sel == 0) ? x_in : ((in_sel == 1) ? g_hA : g_hB);
    float*       out = (out_sel == 1) ? g_hA : g_hB;

    int tid  = threadIdx.x;
    int wid  = tid >> 5, lane = tid & 31;
    int blockStart = blockIdx.x * 32;
    const float4* in4 = (const float4*)in;

    // ---- Phase 1: gather (warp per node, 4 nodes per warp) ----
    for (int q = 0; q < 4; q++) {
        int lr = wid * 4 + q;
        int node = blockStart + lr;
        float4 a0 = make_float4(0.f, 0.f, 0.f, 0.f);
        float4 a1 = make_float4(0.f, 0.f, 0.f, 0.f);
        if (g_m[node] != 0.0f) {
            int b1000 = (node / NN) * NN;
            float D  = g_D[node];
            float wi = g_w[node];
            float4 xv = in4[(size_t)node * 32 + lane];
            a0.x = wi * xv.x; a0.y = wi * xv.y; a0.z = wi * xv.z; a0.w = wi * xv.w;
            int deg = g_deg[node];
            const unsigned short* nb = g_nbr + (size_t)node * MAXD;
            for (int base = 0; base < deg; base += 32) {
                int lim = deg - base; if (lim > 32) lim = 32;
                int myj = 0; float myw = 0.f;
                if (lane < lim) {
                    myj = nb[base + lane];
                    myw = g_w[b1000 + myj];
                }
                int t = 0;
                for (; t + 3 < lim; t += 4) {
                    int   j0 = __shfl_sync(0xffffffffu, myj, t);
                    int   j1 = __shfl_sync(0xffffffffu, myj, t + 1);
                    int   j2 = __shfl_sync(0xffffffffu, myj, t + 2);
                    int   j3 = __shfl_sync(0xffffffffu, myj, t + 3);
                    float w0 = __shfl_sync(0xffffffffu, myw, t);
                    float w1 = __shfl_sync(0xffffffffu, myw, t + 1);
                    float w2 = __shfl_sync(0xffffffffu, myw, t + 2);
                    float w3 = __shfl_sync(0xffffffffu, myw, t + 3);
                    float4 v0 = in4[(size_t)(b1000 + j0) * 32 + lane];
                    float4 v1 = in4[(size_t)(b1000 + j1) * 32 + lane];
                    float4 v2 = in4[(size_t)(b1000 + j2) * 32 + lane];
                    float4 v3 = in4[(size_t)(b1000 + j3) * 32 + lane];
                    a0.x += w0 * v0.x; a0.y += w0 * v0.y; a0.z += w0 * v0.z; a0.w += w0 * v0.w;
                    a1.x += w1 * v1.x; a1.y += w1 * v1.y; a1.z += w1 * v1.z; a1.w += w1 * v1.w;
                    a0.x += w2 * v2.x; a0.y += w2 * v2.y; a0.z += w2 * v2.z; a0.w += w2 * v2.w;
                    a1.x += w3 * v3.x; a1.y += w3 * v3.y; a1.z += w3 * v3.z; a1.w += w3 * v3.w;
                }
                for (; t < lim; t++) {
                    int   j0 = __shfl_sync(0xffffffffu, myj, t);
                    float w0 = __shfl_sync(0xffffffffu, myw, t);
                    float4 v0 = in4[(size_t)(b1000 + j0) * 32 + lane];
                    a0.x += w0 * v0.x; a0.y += w0 * v0.y; a0.z += w0 * v0.z; a0.w += w0 * v0.w;
                }
            }
            a0.x = D * (a0.x + a1.x);
            a0.y = D * (a0.y + a1.y);
            a0.z = D * (a0.z + a1.z);
            a0.w = D * (a0.w + a1.w);
        }
        ((float4*)(sS + lr * 132))[lane] = a0;
    }
    __syncthreads();

    // ---- Phase 2: 32x128 GEMM; W rows from L1 ----
    int tx = tid & 31, ty = tid >> 5;
    const float4* W4 = (const float4*)(g_Wt + layer * FF * FF);
    float acc[4][4];
    #pragma unroll
    for (int j = 0; j < 4; j++)
        #pragma unroll
        for (int c = 0; c < 4; c++) acc[j][c] = 0.0f;

    #pragma unroll 8
    for (int kk = 0; kk < FF; kk += 4) {
        float4 b0 = *(const float4*)&sS[(ty * 4 + 0) * 132 + kk];
        float4 b1 = *(const float4*)&sS[(ty * 4 + 1) * 132 + kk];
        float4 b2 = *(const float4*)&sS[(ty * 4 + 2) * 132 + kk];
        float4 b3 = *(const float4*)&sS[(ty * 4 + 3) * 132 + kk];
        #pragma unroll
        for (int i = 0; i < 4; i++) {
            float4 wv = __ldg(W4 + (kk + i) * 32 + tx);
            float s0 = (i == 0) ? b0.x : (i == 1) ? b0.y : (i == 2) ? b0.z : b0.w;
            float s1 = (i == 0) ? b1.x : (i == 1) ? b1.y : (i == 2) ? b1.z : b1.w;
            float s2 = (i == 0) ? b2.x : (i == 1) ? b2.y : (i == 2) ? b2.z : b2.w;
            float s3 = (i == 0) ? b3.x : (i == 1) ? b3.y : (i == 2) ? b3.z : b3.w;
            acc[0][0] += s0 * wv.x; acc[0][1] += s0 * wv.y; acc[0][2] += s0 * wv.z; acc[0][3] += s0 * wv.w;
            acc[1][0] += s1 * wv.x; acc[1][1] += s1 * wv.y; acc[1][2] += s1 * wv.z; acc[1][3] += s1 * wv.w;
            acc[2][0] += s2 * wv.x; acc[2][1] += s2 * wv.y; acc[2][2] += s2 * wv.z; acc[2][3] += s2 * wv.w;
            acc[3][0] += s3 * wv.x; acc[3][1] += s3 * wv.y; acc[3][2] += s3 * wv.z; acc[3][3] += s3 * wv.w;
        }
    }

    float4 bias4 = __ldg((const float4*)bias + tx);
    float  s2p = 0.f;
    float4 pv  = make_float4(0.f, 0.f, 0.f, 0.f);
    if (p) {
        pv = __ldg((const float4*)p + tx);
        s2p = pv.x * pv.x + pv.y * pv.y + pv.z * pv.z + pv.w * pv.w;
        #pragma unroll
        for (int o = 16; o; o >>= 1) s2p += __shfl_xor_sync(0xffffffffu, s2p, o);
    }

    #pragma unroll
    for (int j = 0; j < 4; j++) {
        int node = blockStart + ty * 4 + j;
        float m = g_m[node];
        float4 o;
        o.x = fmaxf(acc[j][0] + bias4.x, 0.0f) * m;
        o.y = fmaxf(acc[j][1] + bias4.y, 0.0f) * m;
        o.z = fmaxf(acc[j][2] + bias4.z, 0.0f) * m;
        o.w = fmaxf(acc[j][3] + bias4.w, 0.0f) * m;
        ((float4*)(out + (size_t)node * FF))[tx] = o;
        if (p) {
            float s1 = o.x * pv.x + o.y * pv.y + o.z * pv.z + o.w * pv.w;
            #pragma unroll
            for (int of = 16; of; of >>= 1) s1 += __shfl_xor_sync(0xffffffffu, s1, of);
            if (tx == 0) g_y[node] = s1 / sqrtf(s2p);
        }
    }
}

// ---------------- pooling: stable rank, drop N_remove lowest; update m, c ----
__global__ void k_pool(const int* __restrict__ N_nodes, int first) {
    __shared__ float key[NN];
    int b = blockIdx.x, i = threadIdx.x;
    int node = b * NN + i;
    float m = 0.f, yv = 0.f;
    if (i < NN) {
        m  = g_m[node];
        yv = g_y[node];
        key[i] = (m > 0.f) ? yv : __int_as_float(0x7f800000);
    }
    __syncthreads();
    if (i >= NN) return;

    int Nn  = N_nodes[b];
    int Nr1 = (int)((float)Nn * 0.2f);
    int Nr  = first ? Nr1 : (int)((float)(Nn - Nr1) * 0.2f);

    if (m > 0.f) {
        float ki = key[i];
        int cnt = 0;
        #pragma unroll 4
        for (int j = 0; j < NN; j++) {
            float kj = key[j];
            cnt += (kj < ki) || (kj == ki && j < i);
        }
        bool keep = (cnt >= Nr);
        g_m[node] = keep ? 1.0f : 0.0f;
        g_c[node] = keep ? tanhf(yv) : 0.0f;
    } else {
        g_m[node] = 0.0f;
        g_c[node] = 0.0f;
    }
}

// ---------------- global max pool + FC (1024 threads: 8-way segmented) -------
__global__ void k_final(const float* __restrict__ Wfc, const float* __restrict__ bfc,
                        float* __restrict__ outp) {
    __shared__ float red[8][FF];
    __shared__ float gmx[FF];
    int b = blockIdx.x;
    int f = threadIdx.x & 127;
    int g = threadIdx.x >> 7;      // 0..7
    const float* hb = g_hA + (size_t)b * NN * FF + f;
    float mx = 0.0f;
    #pragma unroll 5
    for (int i = g * 125; i < (g + 1) * 125; i++)
        mx = fmaxf(mx, hb[(size_t)i * FF]);
    red[g][f] = mx;
    __syncthreads();
    if (threadIdx.x < FF) {
        float m = red[0][f];
        #pragma unroll
        for (int r = 1; r < 8; r++) m = fmaxf(m, red[r][f]);
        gmx[f] = m;
    }
    __syncthreads();
    if (threadIdx.x < 64) {
        float s = bfc[threadIdx.x];
        #pragma unroll 4
        for (int k = 0; k < FF; k++) s += gmx[k] * Wfc[threadIdx.x * FF + k];
        outp[b * 64 + threadIdx.x] = s;
    }
}

// ---------------- launch ----------------
extern "C" void kernel_launch(void* const* d_in, const int* in_sizes, int n_in,
                              void* d_out, int out_size) {
    const float* x    = (const float*)d_in[0];
    const float* A    = (const float*)d_in[1];
    const float* mask = (const float*)d_in[2];
    const int*   Nn   = (const int*)d_in[3];
    const float* W0   = (const float*)d_in[4];
    const float* b0   = (const float*)d_in[5];
    const float* W1   = (const float*)d_in[6];
    const float* b1   = (const float*)d_in[7];
    const float* W2   = (const float*)d_in[8];
    const float* b2   = (const float*)d_in[9];
    const float* p0   = (const float*)d_in[10];
    const float* p1   = (const float*)d_in[11];
    const float* Wfc  = (const float*)d_in[12];
    const float* bfc  = (const float*)d_in[13];
    float* outp = (float*)d_out;

    k_init <<<192, 256>>>(mask, W0, W1, W2);
    k_build<<<4000, 256>>>(A);

    // layer 0
    k_degD <<<125, 256>>>();
    k_gconv<<<1000, 256>>>(x, 0, 1, 0, b0, p0);   // x -> hA (+scores)
    k_pool <<<32, 1024>>>(Nn, 1);

    // layer 1
    k_degD <<<125, 256>>>();
    k_gconv<<<1000, 256>>>(x, 1, 2, 1, b1, p1);   // hA -> hB (+scores)
    k_pool <<<32, 1024>>>(Nn, 0);

    // layer 2
    k_degD <<<125, 256>>>();
    k_gconv<<<1000, 256>>>(x, 2, 1, 2, b2, (const float*)0); // hB -> hA

    k_final<<<32, 1024>>>(Wfc, bfc, outp);
}

// round 7
// speedup vs baseline: 1.5911x; 1.0582x over previous
#include <cuda_runtime.h>
#include <math.h>

#define BB    32
#define NN    1000
#define FF    128
#define NODES 32000
#define MAXD  128

// ---------------- scratch ----------------
__device__ unsigned short g_nbr[(size_t)NODES * MAXD];
__device__ int            g_deg[NODES];
__device__ float          g_m[NODES];     // current mask (0/1)
__device__ float          g_c[NODES];     // per-node input scale (tanh(y) chain)
__device__ float          g_D[NODES];     // D_i = (deg_hat + 1e-5)^-0.5
__device__ float          g_w[NODES];     // gather weight = D_i * c_i
__device__ float          g_y[NODES];     // pooling scores
__device__ float          g_hA[(size_t)NODES * FF];
__device__ float          g_hB[(size_t)NODES * FF];
__device__ float          g_Wt[3 * FF * FF]; // Wt[l][k*128 + t] = W_l[t][k]
__device__ int            g_vlist[2 * NODES]; // compacted valid node ids per pool
__device__ int            g_bcnt[2 * BB];     // per-batch valid counts per pool

// ---------------- init: masks, scales, weight transpose ----------------
__global__ void k_init(const float* __restrict__ mask,
                       const float* __restrict__ W0,
                       const float* __restrict__ W1,
                       const float* __restrict__ W2) {
    int idx = blockIdx.x * 256 + threadIdx.x;
    if (idx < NODES) { g_m[idx] = mask[idx]; g_c[idx] = 1.0f; }
    if (idx < 3 * FF * FF) {
        int l = idx / (FF * FF);
        int r = idx - l * FF * FF;
        int k = r / FF;
        int t = r - k * FF;
        const float* W = (l == 0) ? W0 : ((l == 1) ? W1 : W2);
        g_Wt[idx] = W[t * FF + k];
    }
}

// ---------------- build adjacency lists: warp per row, float4 + warp scan ----
__global__ void k_build(const float* __restrict__ A) {
    int row  = blockIdx.x * 8 + (threadIdx.x >> 5);
    int lane = threadIdx.x & 31;
    const float4* ar = (const float4*)(A + (size_t)row * NN);
    unsigned short* nb = g_nbr + (size_t)row * MAXD;
    int deg = 0;
    for (int base = 0; base < NN; base += 128) {
        int col = base + 4 * lane;
        float4 v = make_float4(0.f, 0.f, 0.f, 0.f);
        if (col < NN) v = __ldg(ar + (col >> 2));
        unsigned bits = (v.x != 0.f ? 1u : 0u) | (v.y != 0.f ? 2u : 0u)
                      | (v.z != 0.f ? 4u : 0u) | (v.w != 0.f ? 8u : 0u);
        int c = __popc(bits);
        int pre = c;
        #pragma unroll
        for (int off = 1; off < 32; off <<= 1) {
            int t = __shfl_up_sync(0xffffffffu, pre, off);
            if (lane >= off) pre += t;
        }
        int tot = __shfl_sync(0xffffffffu, pre, 31);
        int pos = deg + (pre - c);
        #pragma unroll
        for (int k = 0; k < 4; k++) {
            if (bits & (1u << k)) {
                if (pos < MAXD) nb[pos] = (unsigned short)(col + k);
                pos++;
            }
        }
        deg += tot;
    }
    if (lane == 0) g_deg[row] = (deg < MAXD) ? deg : MAXD;
}

// ---------------- per-layer: degrees -> D, gather weight w = D*c -------------
__global__ void k_degD() {
    int node = blockIdx.x * 256 + threadIdx.x;
    if (node >= NODES) return;
    int b1000 = (node / NN) * NN;
    int deg = g_deg[node];
    const unsigned short* nb = g_nbr + (size_t)node * MAXD;
    float s = 1.0f; // self loop
    #pragma unroll 4
    for (int k = 0; k < deg; k++) s += g_m[b1000 + nb[k]];
    float D = 1.0f / sqrtf(s + 1e-5f);
    g_D[node] = D;
    g_w[node] = D * g_c[node];
}

// ---------------- fused sparse L@x + Linear + ReLU (+ scores), compacted -----
// grid = 32 batches x 32 chunks; block = 256 threads, 32 valid nodes.
// slot < 0: layer-0 identity list (valid = first N_nodes[b] nodes).
// slot >= 0: compacted list g_vlist[slot] with counts g_bcnt[slot].
__global__ void __launch_bounds__(256) k_gconv(
        const float* __restrict__ x_in, int in_sel, int out_sel,
        int layer, const float* __restrict__ bias, const float* __restrict__ p,
        const int* __restrict__ N_nodes, int slot) {
    __shared__ float sS[32 * 132];
    __shared__ int   sNode[32];

    int batch = blockIdx.x >> 5;
    int base  = (blockIdx.x & 31) * 32;
    int count = (slot < 0) ? N_nodes[batch] : g_bcnt[slot * BB + batch];
    if (base >= count) return;

    const float* in  = (in_sel == 0) ? x_in : ((in_sel == 1) ? g_hA : g_hB);
    float*       out = (out_sel == 1) ? g_hA : g_hB;

    int tid  = threadIdx.x;
    int wid  = tid >> 5, lane = tid & 31;
    int b1000 = batch * NN;
    const float4* in4 = (const float4*)in;

    if (tid < 32) {
        int pos = base + tid;
        int nd = -1;
        if (pos < count)
            nd = (slot < 0) ? (b1000 + pos) : g_vlist[slot * NODES + b1000 + pos];
        sNode[tid] = nd;
    }
    __syncthreads();

    // ---- Phase 1: gather (warp per node, 4 nodes per warp) ----
    for (int q = 0; q < 4; q++) {
        int lr = wid * 4 + q;
        int node = sNode[lr];
        float4 a0 = make_float4(0.f, 0.f, 0.f, 0.f);
        float4 a1 = make_float4(0.f, 0.f, 0.f, 0.f);
        if (node >= 0) {
            float D  = g_D[node];
            float wi = g_w[node];
            float4 xv = in4[(size_t)node * 32 + lane];
            a0.x = wi * xv.x; a0.y = wi * xv.y; a0.z = wi * xv.z; a0.w = wi * xv.w;
            int deg = g_deg[node];
            const unsigned short* nb = g_nbr + (size_t)node * MAXD;
            for (int base2 = 0; base2 < deg; base2 += 32) {
                int lim = deg - base2; if (lim > 32) lim = 32;
                int myj = 0; float myw = 0.f;
                if (lane < lim) { myj = nb[base2 + lane]; myw = g_w[b1000 + myj]; }
                int t = 0;
                for (; t + 3 < lim; t += 4) {
                    int   j0 = __shfl_sync(0xffffffffu, myj, t);
                    int   j1 = __shfl_sync(0xffffffffu, myj, t + 1);
                    int   j2 = __shfl_sync(0xffffffffu, myj, t + 2);
                    int   j3 = __shfl_sync(0xffffffffu, myj, t + 3);
                    float w0 = __shfl_sync(0xffffffffu, myw, t);
                    float w1 = __shfl_sync(0xffffffffu, myw, t + 1);
                    float w2 = __shfl_sync(0xffffffffu, myw, t + 2);
                    float w3 = __shfl_sync(0xffffffffu, myw, t + 3);
                    float4 v0 = in4[(size_t)(b1000 + j0) * 32 + lane];
                    float4 v1 = in4[(size_t)(b1000 + j1) * 32 + lane];
                    float4 v2 = in4[(size_t)(b1000 + j2) * 32 + lane];
                    float4 v3 = in4[(size_t)(b1000 + j3) * 32 + lane];
                    a0.x += w0 * v0.x; a0.y += w0 * v0.y; a0.z += w0 * v0.z; a0.w += w0 * v0.w;
                    a1.x += w1 * v1.x; a1.y += w1 * v1.y; a1.z += w1 * v1.z; a1.w += w1 * v1.w;
                    a0.x += w2 * v2.x; a0.y += w2 * v2.y; a0.z += w2 * v2.z; a0.w += w2 * v2.w;
                    a1.x += w3 * v3.x; a1.y += w3 * v3.y; a1.z += w3 * v3.z; a1.w += w3 * v3.w;
                }
                for (; t < lim; t++) {
                    int   j0 = __shfl_sync(0xffffffffu, myj, t);
                    float w0 = __shfl_sync(0xffffffffu, myw, t);
                    float4 v0 = in4[(size_t)(b1000 + j0) * 32 + lane];
                    a0.x += w0 * v0.x; a0.y += w0 * v0.y; a0.z += w0 * v0.z; a0.w += w0 * v0.w;
                }
            }
            a0.x = D * (a0.x + a1.x);
            a0.y = D * (a0.y + a1.y);
            a0.z = D * (a0.z + a1.z);
            a0.w = D * (a0.w + a1.w);
        }
        ((float4*)(sS + lr * 132))[lane] = a0;
    }
    __syncthreads();

    // ---- Phase 2: 32x128 GEMM; W rows from L1 ----
    int tx = tid & 31, ty = tid >> 5;
    const float4* W4 = (const float4*)(g_Wt + layer * FF * FF);
    float acc[4][4];
    #pragma unroll
    for (int j = 0; j < 4; j++)
        #pragma unroll
        for (int c = 0; c < 4; c++) acc[j][c] = 0.0f;

    #pragma unroll 8
    for (int kk = 0; kk < FF; kk += 4) {
        float4 b0 = *(const float4*)&sS[(ty * 4 + 0) * 132 + kk];
        float4 b1 = *(const float4*)&sS[(ty * 4 + 1) * 132 + kk];
        float4 b2 = *(const float4*)&sS[(ty * 4 + 2) * 132 + kk];
        float4 b3 = *(const float4*)&sS[(ty * 4 + 3) * 132 + kk];
        #pragma unroll
        for (int i = 0; i < 4; i++) {
            float4 wv = __ldg(W4 + (kk + i) * 32 + tx);
            float s0 = (i == 0) ? b0.x : (i == 1) ? b0.y : (i == 2) ? b0.z : b0.w;
            float s1 = (i == 0) ? b1.x : (i == 1) ? b1.y : (i == 2) ? b1.z : b1.w;
            float s2 = (i == 0) ? b2.x : (i == 1) ? b2.y : (i == 2) ? b2.z : b2.w;
            float s3 = (i == 0) ? b3.x : (i == 1) ? b3.y : (i == 2) ? b3.z : b3.w;
            acc[0][0] += s0 * wv.x; acc[0][1] += s0 * wv.y; acc[0][2] += s0 * wv.z; acc[0][3] += s0 * wv.w;
            acc[1][0] += s1 * wv.x; acc[1][1] += s1 * wv.y; acc[1][2] += s1 * wv.z; acc[1][3] += s1 * wv.w;
            acc[2][0] += s2 * wv.x; acc[2][1] += s2 * wv.y; acc[2][2] += s2 * wv.z; acc[2][3] += s2 * wv.w;
            acc[3][0] += s3 * wv.x; acc[3][1] += s3 * wv.y; acc[3][2] += s3 * wv.z; acc[3][3] += s3 * wv.w;
        }
    }

    float4 bias4 = __ldg((const float4*)bias + tx);
    float  s2p = 0.f;
    float4 pv  = make_float4(0.f, 0.f, 0.f, 0.f);
    if (p) {
        pv = __ldg((const float4*)p + tx);
        s2p = pv.x * pv.x + pv.y * pv.y + pv.z * pv.z + pv.w * pv.w;
        #pragma unroll
        for (int o = 16; o; o >>= 1) s2p += __shfl_xor_sync(0xffffffffu, s2p, o);
    }

    #pragma unroll
    for (int j = 0; j < 4; j++) {
        int node = sNode[ty * 4 + j];
        float4 o;
        o.x = fmaxf(acc[j][0] + bias4.x, 0.0f);
        o.y = fmaxf(acc[j][1] + bias4.y, 0.0f);
        o.z = fmaxf(acc[j][2] + bias4.z, 0.0f);
        o.w = fmaxf(acc[j][3] + bias4.w, 0.0f);
        if (node >= 0) {
            ((float4*)(out + (size_t)node * FF))[tx] = o;
            if (p) {
                float s1 = o.x * pv.x + o.y * pv.y + o.z * pv.z + o.w * pv.w;
                #pragma unroll
                for (int of = 16; of; of >>= 1) s1 += __shfl_xor_sync(0xffffffffu, s1, of);
                if (tx == 0) g_y[node] = s1 / sqrtf(s2p);
            }
        }
    }
}

// ---------------- pooling: stable rank; update m, c; emit compacted list -----
__global__ void k_pool(const int* __restrict__ N_nodes, int first) {
    __shared__ float key[NN];
    int b = blockIdx.x, i = threadIdx.x;
    int node = b * NN + i;
    float m = 0.f, yv = 0.f;
    if (i < NN) {
        m  = g_m[node];
        yv = g_y[node];
        key[i] = (m > 0.f) ? yv : __int_as_float(0x7f800000);
    }
    __syncthreads();
    int V = __syncthreads_count(m > 0.f);   // # valid nodes this batch

    int Nn  = N_nodes[b];
    int Nr1 = (int)((float)Nn * 0.2f);
    int Nr  = first ? Nr1 : (int)((float)(Nn - Nr1) * 0.2f);
    int slot = first ? 0 : 1;

    if (i < NN) {
        if (m > 0.f) {
            float ki = key[i];
            int cnt = 0;
            #pragma unroll 4
            for (int j = 0; j < NN; j++) {
                float kj = key[j];
                cnt += (kj < ki) || (kj == ki && j < i);   // stable ascending rank
            }
            bool keep = (cnt >= Nr);
            g_m[node] = keep ? 1.0f : 0.0f;
            g_c[node] = keep ? tanhf(yv) : 0.0f;
            if (keep) g_vlist[slot * NODES + b * NN + (cnt - Nr)] = node;
        } else {
            g_m[node] = 0.0f;
            g_c[node] = 0.0f;
        }
    }
    if (i == 0) g_bcnt[slot * BB + b] = V - Nr;
}

// ---------------- global max pool + FC (mask-guarded vs stale rows) ----------
__global__ void k_final(const float* __restrict__ Wfc, const float* __restrict__ bfc,
                        float* __restrict__ outp) {
    __shared__ float red[8][FF];
    __shared__ float gmx[FF];
    int b = blockIdx.x;
    int f = threadIdx.x & 127;
    int g = threadIdx.x >> 7;      // 0..7
    const float* hb = g_hA + (size_t)b * NN * FF + f;
    const float* mb = g_m + b * NN;
    float mx = 0.0f;
    #pragma unroll 5
    for (int i = g * 125; i < (g + 1) * 125; i++)
        mx = fmaxf(mx, hb[(size_t)i * FF] * mb[i]);
    red[g][f] = mx;
    __syncthreads();
    if (threadIdx.x < FF) {
        float m = red[0][f];
        #pragma unroll
        for (int r = 1; r < 8; r++) m = fmaxf(m, red[r][f]);
        gmx[f] = m;
    }
    __syncthreads();
    if (threadIdx.x < 64) {
        float s = bfc[threadIdx.x];
        #pragma unroll 4
        for (int k = 0; k < FF; k++) s += gmx[k] * Wfc[threadIdx.x * FF + k];
        outp[b * 64 + threadIdx.x] = s;
    }
}

// ---------------- launch ----------------
extern "C" void kernel_launch(void* const* d_in, const int* in_sizes, int n_in,
                              void* d_out, int out_size) {
    const float* x    = (const float*)d_in[0];
    const float* A    = (const float*)d_in[1];
    const float* mask = (const float*)d_in[2];
    const int*   Nn   = (const int*)d_in[3];
    const float* W0   = (const float*)d_in[4];
    const float* b0   = (const float*)d_in[5];
    const float* W1   = (const float*)d_in[6];
    const float* b1   = (const float*)d_in[7];
    const float* W2   = (const float*)d_in[8];
    const float* b2   = (const float*)d_in[9];
    const float* p0   = (const float*)d_in[10];
    const float* p1   = (const float*)d_in[11];
    const float* Wfc  = (const float*)d_in[12];
    const float* bfc  = (const float*)d_in[13];
    float* outp = (float*)d_out;

    k_init <<<192, 256>>>(mask, W0, W1, W2);
    k_build<<<4000, 256>>>(A);

    // layer 0: x -> hA (identity valid list: first N_nodes[b] nodes)
    k_degD <<<125, 256>>>();
    k_gconv<<<1024, 256>>>(x, 0, 1, 0, b0, p0, Nn, -1);
    k_pool <<<32, 1024>>>(Nn, 1);

    // layer 1: hA -> hB (compacted list slot 0)
    k_degD <<<125, 256>>>();
    k_gconv<<<1024, 256>>>(x, 1, 2, 1, b1, p1, Nn, 0);
    k_pool <<<32, 1024>>>(Nn, 0);

    // layer 2: hB -> hA (compacted list slot 1)
    k_degD <<<125, 256>>>();
    k_gconv<<<1024, 256>>>(x, 2, 1, 2, b2, (const float*)0, Nn, 1);

    k_final<<<32, 1024>>>(Wfc, bfc, outp);
}